// round 13
// baseline (speedup 1.0000x reference)
#include <cuda_runtime.h>
#include <cuda_bf16.h>
#include <float.h>
#include <math.h>
#include <stdint.h>

// ---------------------------------------------------------------------------
// MEATransformer. Round 12: sims sieve switched bf16->int8 mma.sync
// (m16n8k32.s8.s8.s32): half the MMA instructions (the measured bottleneck:
// legacy mma rt~32/SMSP), exact s32 accumulation, fixed scale 256 quant.
// Candidate sieve (CTA top-4/row) + exact fp32 rescore of union-32 unchanged.
// ---------------------------------------------------------------------------

#define NN       500000
#define DD       256
#define BB       256
#define KK       3
#define NLAB     12
#define NSEQ     768
#define MROWS    2304

#define NCHUNK   15625          // 500000/32 col-chunks
#define NCTA     148
#define NCAND    (NCTA * 4)     // 592 candidates per query
#define QSCALE   256.0f

// ---------------- device scratch --------------------------------------------
__device__ float    g_qn  [BB * DD];
__device__ uint32_t g_q8  [BB * DD / 4];    // int8 q, row-major, 4 k per word
__device__ float g_pv   [BB * NCAND];
__device__ int   g_pi   [BB * NCAND];
__device__ float g_score[NSEQ];
__device__ int   g_idx  [NSEQ];
__device__ int   g_lab  [NSEQ];
__device__ float g_H    [MROWS * DD];
__device__ float g_Qb   [MROWS * DD];
__device__ float g_Kb   [MROWS * DD];
__device__ float g_Vb   [MROWS * DD];
__device__ float g_Ab   [MROWS * DD];
__device__ float g_x    [NSEQ * DD];

// ---------------- helpers ----------------------------------------------------
// pack 4 s32 -> 4 saturated s8 in one b32, v0 in byte0 (lowest k)
__device__ __forceinline__ uint32_t pack_s8x4(int v0, int v1, int v2, int v3) {
    uint32_t r;
    asm("{\n\t.reg .b32 t, z;\n\tmov.b32 z, 0;\n\t"
        "cvt.pack.sat.s8.s32.b32 t, %3, %4, z;\n\t"     // t = v3<<8 | v2
        "cvt.pack.sat.s8.s32.b32 %0, %1, %2, t;\n\t}"   // r = t<<16 | v1<<8 | v0
        : "=r"(r) : "r"(v1), "r"(v0), "r"(v3), "r"(v2));
    return r;
}

__device__ __forceinline__ void mma_s8(int& d0, int& d1, int& d2, int& d3,
                                       uint32_t a0, uint32_t a1, uint32_t a2, uint32_t a3,
                                       uint32_t b0, uint32_t b1) {
    asm volatile("mma.sync.aligned.m16n8k32.row.col.s32.s8.s8.s32 "
                 "{%0,%1,%2,%3}, {%4,%5,%6,%7}, {%8,%9}, {%0,%1,%2,%3};"
                 : "+r"(d0), "+r"(d1), "+r"(d2), "+r"(d3)
                 : "r"(a0), "r"(a1), "r"(a2), "r"(a3), "r"(b0), "r"(b1));
}

__device__ __forceinline__ bool better(float v1, int i1, float v2, int i2) {
    return (v1 > v2) || (v1 == v2 && i1 < i2);   // jax top_k tie-break
}
__device__ __forceinline__ void ins3(float v, int i,
                                     float& v0, int& i0, float& v1, int& i1,
                                     float& v2, int& i2) {
    if (better(v, i, v2, i2)) {
        if (better(v, i, v1, i1)) {
            v2 = v1; i2 = i1;
            if (better(v, i, v0, i0)) { v1 = v0; i1 = i0; v0 = v; i0 = i; }
            else                      { v1 = v;  i1 = i; }
        } else { v2 = v; i2 = i; }
    }
}
__device__ __forceinline__ void ins4f(float v, int i,
                                      float& t0, int& i0, float& t1, int& i1,
                                      float& t2, int& i2, float& t3, int& i3) {
    if (v <= t3) return;
    if (v > t1) {
        if (v > t0) { t3 = t2; i3 = i2; t2 = t1; i2 = i1; t1 = t0; i1 = i0; t0 = v; i0 = i; }
        else        { t3 = t2; i3 = i2; t2 = t1; i2 = i1; t1 = v;  i1 = i; }
    } else {
        if (v > t2) { t3 = t2; i3 = i2; t2 = v; i2 = i; }
        else        { t3 = v;  i3 = i; }
    }
}
__device__ __forceinline__ void ins4i(int v, int i,
                                      int& t0, int& i0, int& t1, int& i1,
                                      int& t2, int& i2, int& t3, int& i3) {
    if (v <= t3) return;
    if (v > t1) {
        if (v > t0) { t3 = t2; i3 = i2; t2 = t1; i2 = i1; t1 = t0; i1 = i0; t0 = v; i0 = i; }
        else        { t3 = t2; i3 = i2; t2 = t1; i2 = i1; t1 = v;  i1 = i; }
    } else {
        if (v > t2) { t3 = t2; i3 = i2; t2 = v; i2 = i; }
        else        { t3 = v;  i3 = i; }
    }
}

// ---------------- kernel 1: normalize queries (+ int8 quant) -----------------
__global__ void normalize_kernel(const float* __restrict__ q) {
    __shared__ float ws[8];
    int b = blockIdx.x, t = threadIdx.x;
    float v = q[b * DD + t];
    float s = v * v;
    #pragma unroll
    for (int o = 16; o; o >>= 1) s += __shfl_xor_sync(0xffffffffu, s, o);
    if ((t & 31) == 0) ws[t >> 5] = s;
    __syncthreads();
    float tot = 0.f;
    #pragma unroll
    for (int w = 0; w < 8; w++) tot += ws[w];
    float qn = v / sqrtf(tot);
    g_qn[b * DD + t] = qn;
    int qi = __float2int_rn(qn * QSCALE);
    qi = max(-127, min(127, qi));
    ((signed char*)g_q8)[b * DD + t] = (signed char)qi;
}

// ---------------- kernel 2: fused sims (fp32 -> int8 frag -> mma.sync s8) ----
// 148 CTAs x 512 threads (16 warps). Warp w owns q rows [16w, 16w+16).
// Per tile (32 cols x 256 k): thread loads 4 adjacent k-rows x 4 n (4 LDG.128),
// packs per-n b32 words (4 k each, byte0 = lowest k), STS to fragment layout.
// IMMA m16n8k32: 8 ksteps; B frag lane = (n&7)<<2 | tig, b0: k-off<16, b1: >=16.
// uint4 slot idx = (nt*4 + ks/2)*32 + lane; comps {x,y}=even ks, {z,w}=odd ks.
__global__ void __launch_bounds__(512, 1) sims_mma_kernel(const float* __restrict__ w) {
    __shared__ uint4 sB[2][512];          // 2 x 8KB fragment buffers
    const int tid = threadIdx.x;
    const int wid = tid >> 5, lane = tid & 31;
    const int g = lane >> 2, qk = lane & 3;
    const int bx = blockIdx.x;
    const int row0 = wid * 16 + g;

    // ---- persistent A fragments: 8 ksteps x 4 regs (int8 packed) ----
    uint32_t Af[8][4];
    #pragma unroll
    for (int ks = 0; ks < 8; ks++) {
        int wbase = row0 * 64 + ks * 8 + qk;       // word idx: row*64 + ks*8 + tig
        Af[ks][0] = g_q8[wbase];                   // row0,   k .. k+15 slice
        Af[ks][1] = g_q8[wbase + 8 * 64];          // row0+8
        Af[ks][2] = g_q8[wbase + 4];               // row0,   k+16 ..
        Af[ks][3] = g_q8[wbase + 8 * 64 + 4];      // row0+8, k+16 ..
    }

    const int ntiles = (NCHUNK - bx + NCTA - 1) / NCTA;

    int va0 = INT_MIN, va1 = INT_MIN, va2 = INT_MIN, va3 = INT_MIN;
    int ja0 = 0x7fffffff, ja1 = 0x7fffffff, ja2 = 0x7fffffff, ja3 = 0x7fffffff;
    int vb0 = INT_MIN, vb1 = INT_MIN, vb2 = INT_MIN, vb3 = INT_MIN;
    int jb0 = 0x7fffffff, jb1 = 0x7fffffff, jb2 = 0x7fffffff, jb3 = 0x7fffffff;

    // conversion assignment: dg = tid>>3 (k-group of 4), n4 = (tid&7)*4
    const int d0 = (tid >> 3) * 4;
    const int n4 = (tid & 7) * 4;
    const int ks = d0 >> 5;
    const int ko = d0 & 31;
    const int tig = (ko & 15) >> 2;
    const int comp = ((ks & 1) << 1) + (ko < 16 ? 0 : 1);   // word within uint4
    const int jj = ks >> 1;

    float4 pf[4];   // 4 k-rows x 4 n prefetch

    auto ldg_tile = [&](int tile) {
        const size_t col0 = (size_t)tile * 32;
        const float* base = w + (size_t)d0 * NN + col0 + n4;
        pf[0] = *(const float4*)(base);
        pf[1] = *(const float4*)(base + NN);
        pf[2] = *(const float4*)(base + 2 * (size_t)NN);
        pf[3] = *(const float4*)(base + 3 * (size_t)NN);
    };
    auto sts_tile = [&](int buf) {
        uint32_t* dst = (uint32_t*)&sB[buf][0];
        const float* p0 = (const float*)&pf[0];
        const float* p1 = (const float*)&pf[1];
        const float* p2 = (const float*)&pf[2];
        const float* p3 = (const float*)&pf[3];
        #pragma unroll
        for (int i = 0; i < 4; i++) {
            int n = n4 + i;
            uint32_t word = pack_s8x4(__float2int_rn(p0[i] * QSCALE),
                                      __float2int_rn(p1[i] * QSCALE),
                                      __float2int_rn(p2[i] * QSCALE),
                                      __float2int_rn(p3[i] * QSCALE));
            int lane2 = ((n & 7) << 2) | tig;
            int f = ((n >> 3) * 4 + jj) * 32 + lane2;
            dst[f * 4 + comp] = word;
        }
    };

    ldg_tile(bx);   // prologue

    for (int t = 0; t < ntiles; t++) {
        const int buf = t & 1;
        sts_tile(buf);
        __syncthreads();
        if (t + 1 < ntiles) ldg_tile(bx + (t + 1) * NCTA);

        const int colbase = (bx + t * NCTA) * 32 + qk * 2;
        #pragma unroll
        for (int nt = 0; nt < 4; nt++) {
            int d0a = 0, d1a = 0, d2a = 0, d3a = 0;
            #pragma unroll
            for (int j = 0; j < 4; j++) {
                uint4 bf = sB[buf][(nt * 4 + j) * 32 + lane];
                mma_s8(d0a, d1a, d2a, d3a,
                       Af[2*j][0], Af[2*j][1], Af[2*j][2], Af[2*j][3],
                       bf.x, bf.y);
                mma_s8(d0a, d1a, d2a, d3a,
                       Af[2*j+1][0], Af[2*j+1][1], Af[2*j+1][2], Af[2*j+1][3],
                       bf.z, bf.w);
            }
            int c0 = colbase + nt * 8;
            ins4i(d0a, c0,     va0, ja0, va1, ja1, va2, ja2, va3, ja3);
            ins4i(d1a, c0 + 1, va0, ja0, va1, ja1, va2, ja2, va3, ja3);
            ins4i(d2a, c0,     vb0, jb0, vb1, jb1, vb2, jb2, vb3, jb3);
            ins4i(d3a, c0 + 1, vb0, jb0, vb1, jb1, vb2, jb2, vb3, jb3);
        }
        __syncthreads();   // all warps done with sB[buf] before next sts_tile
    }

    // ---- merge top-4 across the 4 lanes of each quad ----
    #pragma unroll
    for (int m = 1; m <= 2; m <<= 1) {
        int r0 = __shfl_xor_sync(0xffffffffu, va0, m, 4);
        int r1 = __shfl_xor_sync(0xffffffffu, va1, m, 4);
        int r2 = __shfl_xor_sync(0xffffffffu, va2, m, 4);
        int r3 = __shfl_xor_sync(0xffffffffu, va3, m, 4);
        int s0 = __shfl_xor_sync(0xffffffffu, ja0, m, 4);
        int s1 = __shfl_xor_sync(0xffffffffu, ja1, m, 4);
        int s2 = __shfl_xor_sync(0xffffffffu, ja2, m, 4);
        int s3 = __shfl_xor_sync(0xffffffffu, ja3, m, 4);
        ins4i(r0, s0, va0, ja0, va1, ja1, va2, ja2, va3, ja3);
        ins4i(r1, s1, va0, ja0, va1, ja1, va2, ja2, va3, ja3);
        ins4i(r2, s2, va0, ja0, va1, ja1, va2, ja2, va3, ja3);
        ins4i(r3, s3, va0, ja0, va1, ja1, va2, ja2, va3, ja3);
        r0 = __shfl_xor_sync(0xffffffffu, vb0, m, 4);
        r1 = __shfl_xor_sync(0xffffffffu, vb1, m, 4);
        r2 = __shfl_xor_sync(0xffffffffu, vb2, m, 4);
        r3 = __shfl_xor_sync(0xffffffffu, vb3, m, 4);
        s0 = __shfl_xor_sync(0xffffffffu, jb0, m, 4);
        s1 = __shfl_xor_sync(0xffffffffu, jb1, m, 4);
        s2 = __shfl_xor_sync(0xffffffffu, jb2, m, 4);
        s3 = __shfl_xor_sync(0xffffffffu, jb3, m, 4);
        ins4i(r0, s0, vb0, jb0, vb1, jb1, vb2, jb2, vb3, jb3);
        ins4i(r1, s1, vb0, jb0, vb1, jb1, vb2, jb2, vb3, jb3);
        ins4i(r2, s2, vb0, jb0, vb1, jb1, vb2, jb2, vb3, jb3);
        ins4i(r3, s3, vb0, jb0, vb1, jb1, vb2, jb2, vb3, jb3);
    }
    if (qk == 0) {
        int base = row0 * NCAND + bx * 4;
        g_pv[base + 0] = (float)va0; g_pi[base + 0] = ja0;
        g_pv[base + 1] = (float)va1; g_pi[base + 1] = ja1;
        g_pv[base + 2] = (float)va2; g_pi[base + 2] = ja2;
        g_pv[base + 3] = (float)va3; g_pi[base + 3] = ja3;
        base = (row0 + 8) * NCAND + bx * 4;
        g_pv[base + 0] = (float)vb0; g_pi[base + 0] = jb0;
        g_pv[base + 1] = (float)vb1; g_pi[base + 1] = jb1;
        g_pv[base + 2] = (float)vb2; g_pi[base + 2] = jb2;
        g_pv[base + 3] = (float)vb3; g_pi[base + 3] = jb3;
    }
}

// ---------------- kernel 3: parallel merge + exact rescore + top-3 ----------
__global__ void merge_rescore_kernel(const float* __restrict__ w,
                                     const int* __restrict__ label) {
    __shared__ float cv[NCAND];
    __shared__ int   ci[NCAND];
    __shared__ float qrow[DD];
    __shared__ float c32v[32];
    __shared__ int   c32i[32];
    __shared__ float exv[32];
    int q = blockIdx.x, t = threadIdx.x;
    int wid = t >> 5, lane = t & 31;
    qrow[t] = g_qn[q * DD + t];
    for (int j = t; j < NCAND; j += 256) {
        cv[j] = g_pv[q * NCAND + j];
        ci[j] = g_pi[q * NCAND + j];
    }
    __syncthreads();

    float t0 = -FLT_MAX, t1 = -FLT_MAX, t2 = -FLT_MAX, t3 = -FLT_MAX;
    int   i0 = 0x7fffffff, i1 = 0x7fffffff, i2 = 0x7fffffff, i3 = 0x7fffffff;
    const int lo = wid * 74, hi = lo + 74;
    for (int j = lo + lane; j < hi; j += 32)
        ins4f(cv[j], ci[j], t0, i0, t1, i1, t2, i2, t3, i3);
    #pragma unroll
    for (int m = 16; m >= 1; m >>= 1) {
        float r0 = __shfl_xor_sync(0xffffffffu, t0, m);
        float r1 = __shfl_xor_sync(0xffffffffu, t1, m);
        float r2 = __shfl_xor_sync(0xffffffffu, t2, m);
        float r3 = __shfl_xor_sync(0xffffffffu, t3, m);
        int   s0 = __shfl_xor_sync(0xffffffffu, i0, m);
        int   s1 = __shfl_xor_sync(0xffffffffu, i1, m);
        int   s2 = __shfl_xor_sync(0xffffffffu, i2, m);
        int   s3 = __shfl_xor_sync(0xffffffffu, i3, m);
        ins4f(r0, s0, t0, i0, t1, i1, t2, i2, t3, i3);
        ins4f(r1, s1, t0, i0, t1, i1, t2, i2, t3, i3);
        ins4f(r2, s2, t0, i0, t1, i1, t2, i2, t3, i3);
        ins4f(r3, s3, t0, i0, t1, i1, t2, i2, t3, i3);
    }
    if (lane == 0) {
        c32v[wid * 4 + 0] = t0; c32i[wid * 4 + 0] = i0;
        c32v[wid * 4 + 1] = t1; c32i[wid * 4 + 1] = i1;
        c32v[wid * 4 + 2] = t2; c32i[wid * 4 + 2] = i2;
        c32v[wid * 4 + 3] = t3; c32i[wid * 4 + 3] = i3;
    }
    __syncthreads();

    {
        int c = t >> 3, sub = t & 7;
        int idx = c32i[c];
        float acc = 0.f;
        #pragma unroll
        for (int dd = 0; dd < 32; dd++) {
            int d = sub * 32 + dd;
            acc += qrow[d] * w[(size_t)d * NN + idx];
        }
        #pragma unroll
        for (int m = 4; m >= 1; m >>= 1)
            acc += __shfl_xor_sync(0xffffffffu, acc, m, 8);
        if (sub == 0) exv[c] = acc;
    }
    __syncthreads();

    if (t == 0) {
        float f0 = -FLT_MAX, f1 = -FLT_MAX, f2 = -FLT_MAX;
        int   j0 = 0x7fffffff, j1 = 0x7fffffff, j2 = 0x7fffffff;
        for (int k = 0; k < 32; k++)
            ins3(exv[k], c32i[k], f0, j0, f1, j1, f2, j2);
        g_score[q * 3 + 0] = f0; g_idx[q * 3 + 0] = j0; g_lab[q * 3 + 0] = label[j0];
        g_score[q * 3 + 1] = f1; g_idx[q * 3 + 1] = j1; g_lab[q * 3 + 1] = label[j1];
        g_score[q * 3 + 2] = f2; g_idx[q * 3 + 2] = j2; g_lab[q * 3 + 2] = label[j2];
    }
}

// ---------------- kernel 4: build H (gather) ---------------------------------
__global__ void build_h_kernel(const float* __restrict__ queries,
                               const float* __restrict__ w) {
    int s = blockIdx.x, d = threadIdx.x;
    int b = s / KK;
    int lab = g_lab[s];
    float score = g_score[s];
    int idx = g_idx[s];
    float* Hrow = &g_H[s * 3 * DD];
    Hrow[d]          = (d == lab) ? score : 0.f;
    Hrow[DD + d]     = queries[b * DD + d];
    Hrow[2 * DD + d] = w[(size_t)d * NN + idx];
}

// ---------------- tail (proven) ----------------------------------------------
__global__ void qkv_kernel(const float* __restrict__ Wq, const float* __restrict__ bq,
                           const float* __restrict__ Wk, const float* __restrict__ bk,
                           const float* __restrict__ Wv, const float* __restrict__ bv) {
    __shared__ float h[16][DD];
    int r0 = blockIdx.x * 16, t = threadIdx.x;
    #pragma unroll
    for (int i = 0; i < 16; i++) h[i][t] = g_H[(r0 + i) * DD + t];
    __syncthreads();
    float aq[16], ak[16], av[16];
    #pragma unroll
    for (int i = 0; i < 16; i++) { aq[i] = bq[t]; ak[i] = bk[t]; av[i] = bv[t]; }
    for (int d = 0; d < DD; d++) {
        float wq = Wq[d * DD + t], wk = Wk[d * DD + t], wv = Wv[d * DD + t];
        #pragma unroll
        for (int i = 0; i < 16; i++) {
            float hv = h[i][d];
            aq[i] += hv * wq; ak[i] += hv * wk; av[i] += hv * wv;
        }
    }
    #pragma unroll
    for (int i = 0; i < 16; i++) {
        g_Qb[(r0 + i) * DD + t] = aq[i];
        g_Kb[(r0 + i) * DD + t] = ak[i];
        g_Vb[(r0 + i) * DD + t] = av[i];
    }
}

__global__ void attn_kernel() {
    __shared__ float q[3][DD], k[3][DD], v[3][DD], a[9];
    int s = blockIdx.x, t = threadIdx.x;
    int base = s * 3 * DD;
    #pragma unroll
    for (int i = 0; i < 3; i++) {
        q[i][t] = g_Qb[base + i * DD + t];
        k[i][t] = g_Kb[base + i * DD + t];
        v[i][t] = g_Vb[base + i * DD + t];
    }
    __syncthreads();
    if (t < 9) {
        int i = t / 3, j = t % 3;
        float acc = 0.f;
        for (int d = 0; d < DD; d++) acc += q[i][d] * k[j][d];
        a[t] = acc * 0.125f;
    }
    __syncthreads();
    if (t < 3) {
        float m0 = fmaxf(a[t*3], fmaxf(a[t*3+1], a[t*3+2]));
        float e0 = expf(a[t*3] - m0), e1 = expf(a[t*3+1] - m0), e2 = expf(a[t*3+2] - m0);
        float inv = 1.f / (e0 + e1 + e2);
        a[t*3] = e0 * inv; a[t*3+1] = e1 * inv; a[t*3+2] = e2 * inv;
    }
    __syncthreads();
    #pragma unroll
    for (int i = 0; i < 3; i++)
        g_Ab[base + i * DD + t] = a[i*3] * v[0][t] + a[i*3+1] * v[1][t] + a[i*3+2] * v[2][t];
}

__global__ void oproj_kernel(const float* __restrict__ Wo, const float* __restrict__ bo) {
    __shared__ float h[16][DD];
    int r0 = blockIdx.x * 16, t = threadIdx.x;
    #pragma unroll
    for (int i = 0; i < 16; i++) h[i][t] = g_Ab[(r0 + i) * DD + t];
    __syncthreads();
    float ao[16];
    #pragma unroll
    for (int i = 0; i < 16; i++) ao[i] = bo[t];
    for (int d = 0; d < DD; d++) {
        float wo = Wo[d * DD + t];
        #pragma unroll
        for (int i = 0; i < 16; i++) ao[i] += h[i][d] * wo;
    }
    #pragma unroll
    for (int i = 0; i < 16; i++) g_H[(r0 + i) * DD + t] = ao[i];
}

__global__ void dense_kernel(const float* __restrict__ W, const float* __restrict__ b) {
    __shared__ float h[DD];
    int s = blockIdx.x, t = threadIdx.x;
    h[t] = g_H[s * 3 * DD + t];
    __syncthreads();
    float acc = b[t];
    for (int d = 0; d < DD; d++) acc += h[d] * W[d * DD + t];
    g_x[s * DD + t] = tanhf(acc);
}

__global__ void final_kernel(const float* __restrict__ out_w,
                             const float* __restrict__ out_b,
                             float* __restrict__ out) {
    __shared__ float lg[36];
    int b = blockIdx.x, t = threadIdx.x;
    int k = t / NLAB, l = t % NLAB;
    float acc = out_b[l];
    const float* x = &g_x[(b * 3 + k) * DD];
    for (int d = 0; d < DD; d++) acc += x[d] * out_w[d * NLAB + l];
    lg[t] = acc;
    __syncthreads();
    if (t < NLAB) {
        float mean = (lg[t] + lg[NLAB + t] + lg[2 * NLAB + t]) * (1.f / 3.f);
        int l0 = g_lab[b * 3], l1 = g_lab[b * 3 + 1], l2 = g_lab[b * 3 + 2];
        float cnt = (float)((l0 == t) + (l1 == t) + (l2 == t));
        out[b * NLAB + t] = 0.5f * mean + 0.5f * (cnt * (1.f / 3.f));
    }
}

// ---------------- launcher ---------------------------------------------------
extern "C" void kernel_launch(void* const* d_in, const int* in_sizes, int n_in,
                              void* d_out, int out_size) {
    const float* queries = (const float*)d_in[0];
    const float* weight  = (const float*)d_in[1];
    const int*   label   = (const int*)  d_in[2];
    const float* Wq      = (const float*)d_in[3];
    const float* bq      = (const float*)d_in[4];
    const float* Wk      = (const float*)d_in[5];
    const float* bk      = (const float*)d_in[6];
    const float* Wv      = (const float*)d_in[7];
    const float* bv      = (const float*)d_in[8];
    const float* Wo      = (const float*)d_in[9];
    const float* bo      = (const float*)d_in[10];
    const float* dense_w = (const float*)d_in[11];
    const float* dense_b = (const float*)d_in[12];
    const float* out_w   = (const float*)d_in[13];
    const float* out_b   = (const float*)d_in[14];
    float* out = (float*)d_out;

    normalize_kernel<<<BB, DD>>>(queries);
    sims_mma_kernel<<<NCTA, 512>>>(weight);
    merge_rescore_kernel<<<BB, 256>>>(weight, label);
    build_h_kernel<<<NSEQ, DD>>>(queries, weight);

    for (int l = 0; l < 2; l++) {
        qkv_kernel<<<MROWS / 16, DD>>>(Wq + l * DD * DD, bq + l * DD,
                                       Wk + l * DD * DD, bk + l * DD,
                                       Wv + l * DD * DD, bv + l * DD);
        attn_kernel<<<NSEQ, DD>>>();
        oproj_kernel<<<MROWS / 16, DD>>>(Wo + l * DD * DD, bo + l * DD);
    }
    dense_kernel<<<NSEQ, DD>>>(dense_w, dense_b);
    final_kernel<<<BB, 36>>>(out_w, out_b, out);
}

// round 14
// speedup vs baseline: 1.0017x; 1.0017x over previous
#include <cuda_runtime.h>
#include <cuda_bf16.h>
#include <float.h>
#include <math.h>
#include <stdint.h>

// ---------------------------------------------------------------------------
// MEATransformer. Round 12: sims sieve switched bf16->int8 mma.sync
// (m16n8k32.s8.s8.s32): half the MMA instructions (the measured bottleneck:
// legacy mma rt~32/SMSP), exact s32 accumulation, fixed scale 256 quant.
// Candidate sieve (CTA top-4/row) + exact fp32 rescore of union-32 unchanged.
// ---------------------------------------------------------------------------

#define NN       500000
#define DD       256
#define BB       256
#define KK       3
#define NLAB     12
#define NSEQ     768
#define MROWS    2304

#define NCHUNK   15625          // 500000/32 col-chunks
#define NCTA     148
#define NCAND    (NCTA * 4)     // 592 candidates per query
#define QSCALE   256.0f

// ---------------- device scratch --------------------------------------------
__device__ float    g_qn  [BB * DD];
__device__ uint32_t g_q8  [BB * DD / 4];    // int8 q, row-major, 4 k per word
__device__ float g_pv   [BB * NCAND];
__device__ int   g_pi   [BB * NCAND];
__device__ float g_score[NSEQ];
__device__ int   g_idx  [NSEQ];
__device__ int   g_lab  [NSEQ];
__device__ float g_H    [MROWS * DD];
__device__ float g_Qb   [MROWS * DD];
__device__ float g_Kb   [MROWS * DD];
__device__ float g_Vb   [MROWS * DD];
__device__ float g_Ab   [MROWS * DD];
__device__ float g_x    [NSEQ * DD];

// ---------------- helpers ----------------------------------------------------
// pack 4 s32 -> 4 saturated s8 in one b32, v0 in byte0 (lowest k)
__device__ __forceinline__ uint32_t pack_s8x4(int v0, int v1, int v2, int v3) {
    uint32_t r;
    asm("{\n\t.reg .b32 t, z;\n\tmov.b32 z, 0;\n\t"
        "cvt.pack.sat.s8.s32.b32 t, %3, %4, z;\n\t"     // t = v3<<8 | v2
        "cvt.pack.sat.s8.s32.b32 %0, %1, %2, t;\n\t}"   // r = t<<16 | v1<<8 | v0
        : "=r"(r) : "r"(v1), "r"(v0), "r"(v3), "r"(v2));
    return r;
}

__device__ __forceinline__ void mma_s8(int& d0, int& d1, int& d2, int& d3,
                                       uint32_t a0, uint32_t a1, uint32_t a2, uint32_t a3,
                                       uint32_t b0, uint32_t b1) {
    asm volatile("mma.sync.aligned.m16n8k32.row.col.s32.s8.s8.s32 "
                 "{%0,%1,%2,%3}, {%4,%5,%6,%7}, {%8,%9}, {%0,%1,%2,%3};"
                 : "+r"(d0), "+r"(d1), "+r"(d2), "+r"(d3)
                 : "r"(a0), "r"(a1), "r"(a2), "r"(a3), "r"(b0), "r"(b1));
}

__device__ __forceinline__ bool better(float v1, int i1, float v2, int i2) {
    return (v1 > v2) || (v1 == v2 && i1 < i2);   // jax top_k tie-break
}
__device__ __forceinline__ void ins3(float v, int i,
                                     float& v0, int& i0, float& v1, int& i1,
                                     float& v2, int& i2) {
    if (better(v, i, v2, i2)) {
        if (better(v, i, v1, i1)) {
            v2 = v1; i2 = i1;
            if (better(v, i, v0, i0)) { v1 = v0; i1 = i0; v0 = v; i0 = i; }
            else                      { v1 = v;  i1 = i; }
        } else { v2 = v; i2 = i; }
    }
}
__device__ __forceinline__ void ins4f(float v, int i,
                                      float& t0, int& i0, float& t1, int& i1,
                                      float& t2, int& i2, float& t3, int& i3) {
    if (v <= t3) return;
    if (v > t1) {
        if (v > t0) { t3 = t2; i3 = i2; t2 = t1; i2 = i1; t1 = t0; i1 = i0; t0 = v; i0 = i; }
        else        { t3 = t2; i3 = i2; t2 = t1; i2 = i1; t1 = v;  i1 = i; }
    } else {
        if (v > t2) { t3 = t2; i3 = i2; t2 = v; i2 = i; }
        else        { t3 = v;  i3 = i; }
    }
}
__device__ __forceinline__ void ins4i(int v, int i,
                                      int& t0, int& i0, int& t1, int& i1,
                                      int& t2, int& i2, int& t3, int& i3) {
    if (v <= t3) return;
    if (v > t1) {
        if (v > t0) { t3 = t2; i3 = i2; t2 = t1; i2 = i1; t1 = t0; i1 = i0; t0 = v; i0 = i; }
        else        { t3 = t2; i3 = i2; t2 = t1; i2 = i1; t1 = v;  i1 = i; }
    } else {
        if (v > t2) { t3 = t2; i3 = i2; t2 = v; i2 = i; }
        else        { t3 = v;  i3 = i; }
    }
}

// ---------------- kernel 1: normalize queries (+ int8 quant) -----------------
__global__ void normalize_kernel(const float* __restrict__ q) {
    __shared__ float ws[8];
    int b = blockIdx.x, t = threadIdx.x;
    float v = q[b * DD + t];
    float s = v * v;
    #pragma unroll
    for (int o = 16; o; o >>= 1) s += __shfl_xor_sync(0xffffffffu, s, o);
    if ((t & 31) == 0) ws[t >> 5] = s;
    __syncthreads();
    float tot = 0.f;
    #pragma unroll
    for (int w = 0; w < 8; w++) tot += ws[w];
    float qn = v / sqrtf(tot);
    g_qn[b * DD + t] = qn;
    int qi = __float2int_rn(qn * QSCALE);
    qi = max(-127, min(127, qi));
    ((signed char*)g_q8)[b * DD + t] = (signed char)qi;
}

// ---------------- kernel 2: fused sims (fp32 -> int8 frag -> mma.sync s8) ----
// 148 CTAs x 512 threads (16 warps). Warp w owns q rows [16w, 16w+16).
// Per tile (32 cols x 256 k): thread loads 4 adjacent k-rows x 4 n (4 LDG.128),
// packs per-n b32 words (4 k each, byte0 = lowest k), STS to fragment layout.
// IMMA m16n8k32: 8 ksteps; B frag lane = (n&7)<<2 | tig, b0: k-off<16, b1: >=16.
// uint4 slot idx = (nt*4 + ks/2)*32 + lane; comps {x,y}=even ks, {z,w}=odd ks.
__global__ void __launch_bounds__(512, 1) sims_mma_kernel(const float* __restrict__ w) {
    __shared__ uint4 sB[2][512];          // 2 x 8KB fragment buffers
    const int tid = threadIdx.x;
    const int wid = tid >> 5, lane = tid & 31;
    const int g = lane >> 2, qk = lane & 3;
    const int bx = blockIdx.x;
    const int row0 = wid * 16 + g;

    // ---- persistent A fragments: 8 ksteps x 4 regs (int8 packed) ----
    uint32_t Af[8][4];
    #pragma unroll
    for (int ks = 0; ks < 8; ks++) {
        int wbase = row0 * 64 + ks * 8 + qk;       // word idx: row*64 + ks*8 + tig
        Af[ks][0] = g_q8[wbase];                   // row0,   k .. k+15 slice
        Af[ks][1] = g_q8[wbase + 8 * 64];          // row0+8
        Af[ks][2] = g_q8[wbase + 4];               // row0,   k+16 ..
        Af[ks][3] = g_q8[wbase + 8 * 64 + 4];      // row0+8, k+16 ..
    }

    const int ntiles = (NCHUNK - bx + NCTA - 1) / NCTA;

    int va0 = INT_MIN, va1 = INT_MIN, va2 = INT_MIN, va3 = INT_MIN;
    int ja0 = 0x7fffffff, ja1 = 0x7fffffff, ja2 = 0x7fffffff, ja3 = 0x7fffffff;
    int vb0 = INT_MIN, vb1 = INT_MIN, vb2 = INT_MIN, vb3 = INT_MIN;
    int jb0 = 0x7fffffff, jb1 = 0x7fffffff, jb2 = 0x7fffffff, jb3 = 0x7fffffff;

    // conversion assignment: dg = tid>>3 (k-group of 4), n4 = (tid&7)*4
    const int d0 = (tid >> 3) * 4;
    const int n4 = (tid & 7) * 4;
    const int ks = d0 >> 5;
    const int ko = d0 & 31;
    const int tig = (ko & 15) >> 2;
    const int comp = ((ks & 1) << 1) + (ko < 16 ? 0 : 1);   // word within uint4
    const int jj = ks >> 1;

    float4 pf[4];   // 4 k-rows x 4 n prefetch

    auto ldg_tile = [&](int tile) {
        const size_t col0 = (size_t)tile * 32;
        const float* base = w + (size_t)d0 * NN + col0 + n4;
        pf[0] = *(const float4*)(base);
        pf[1] = *(const float4*)(base + NN);
        pf[2] = *(const float4*)(base + 2 * (size_t)NN);
        pf[3] = *(const float4*)(base + 3 * (size_t)NN);
    };
    auto sts_tile = [&](int buf) {
        uint32_t* dst = (uint32_t*)&sB[buf][0];
        const float* p0 = (const float*)&pf[0];
        const float* p1 = (const float*)&pf[1];
        const float* p2 = (const float*)&pf[2];
        const float* p3 = (const float*)&pf[3];
        #pragma unroll
        for (int i = 0; i < 4; i++) {
            int n = n4 + i;
            uint32_t word = pack_s8x4(__float2int_rn(p0[i] * QSCALE),
                                      __float2int_rn(p1[i] * QSCALE),
                                      __float2int_rn(p2[i] * QSCALE),
                                      __float2int_rn(p3[i] * QSCALE));
            int lane2 = ((n & 7) << 2) | tig;
            int f = ((n >> 3) * 4 + jj) * 32 + lane2;
            dst[f * 4 + comp] = word;
        }
    };

    ldg_tile(bx);   // prologue

    for (int t = 0; t < ntiles; t++) {
        const int buf = t & 1;
        sts_tile(buf);
        __syncthreads();
        if (t + 1 < ntiles) ldg_tile(bx + (t + 1) * NCTA);

        const int colbase = (bx + t * NCTA) * 32 + qk * 2;
        #pragma unroll
        for (int nt = 0; nt < 4; nt++) {
            int d0a = 0, d1a = 0, d2a = 0, d3a = 0;
            #pragma unroll
            for (int j = 0; j < 4; j++) {
                uint4 bf = sB[buf][(nt * 4 + j) * 32 + lane];
                mma_s8(d0a, d1a, d2a, d3a,
                       Af[2*j][0], Af[2*j][1], Af[2*j][2], Af[2*j][3],
                       bf.x, bf.y);
                mma_s8(d0a, d1a, d2a, d3a,
                       Af[2*j+1][0], Af[2*j+1][1], Af[2*j+1][2], Af[2*j+1][3],
                       bf.z, bf.w);
            }
            int c0 = colbase + nt * 8;
            ins4i(d0a, c0,     va0, ja0, va1, ja1, va2, ja2, va3, ja3);
            ins4i(d1a, c0 + 1, va0, ja0, va1, ja1, va2, ja2, va3, ja3);
            ins4i(d2a, c0,     vb0, jb0, vb1, jb1, vb2, jb2, vb3, jb3);
            ins4i(d3a, c0 + 1, vb0, jb0, vb1, jb1, vb2, jb2, vb3, jb3);
        }
        __syncthreads();   // all warps done with sB[buf] before next sts_tile
    }

    // ---- merge top-4 across the 4 lanes of each quad ----
    #pragma unroll
    for (int m = 1; m <= 2; m <<= 1) {
        int r0 = __shfl_xor_sync(0xffffffffu, va0, m, 4);
        int r1 = __shfl_xor_sync(0xffffffffu, va1, m, 4);
        int r2 = __shfl_xor_sync(0xffffffffu, va2, m, 4);
        int r3 = __shfl_xor_sync(0xffffffffu, va3, m, 4);
        int s0 = __shfl_xor_sync(0xffffffffu, ja0, m, 4);
        int s1 = __shfl_xor_sync(0xffffffffu, ja1, m, 4);
        int s2 = __shfl_xor_sync(0xffffffffu, ja2, m, 4);
        int s3 = __shfl_xor_sync(0xffffffffu, ja3, m, 4);
        ins4i(r0, s0, va0, ja0, va1, ja1, va2, ja2, va3, ja3);
        ins4i(r1, s1, va0, ja0, va1, ja1, va2, ja2, va3, ja3);
        ins4i(r2, s2, va0, ja0, va1, ja1, va2, ja2, va3, ja3);
        ins4i(r3, s3, va0, ja0, va1, ja1, va2, ja2, va3, ja3);
        r0 = __shfl_xor_sync(0xffffffffu, vb0, m, 4);
        r1 = __shfl_xor_sync(0xffffffffu, vb1, m, 4);
        r2 = __shfl_xor_sync(0xffffffffu, vb2, m, 4);
        r3 = __shfl_xor_sync(0xffffffffu, vb3, m, 4);
        s0 = __shfl_xor_sync(0xffffffffu, jb0, m, 4);
        s1 = __shfl_xor_sync(0xffffffffu, jb1, m, 4);
        s2 = __shfl_xor_sync(0xffffffffu, jb2, m, 4);
        s3 = __shfl_xor_sync(0xffffffffu, jb3, m, 4);
        ins4i(r0, s0, vb0, jb0, vb1, jb1, vb2, jb2, vb3, jb3);
        ins4i(r1, s1, vb0, jb0, vb1, jb1, vb2, jb2, vb3, jb3);
        ins4i(r2, s2, vb0, jb0, vb1, jb1, vb2, jb2, vb3, jb3);
        ins4i(r3, s3, vb0, jb0, vb1, jb1, vb2, jb2, vb3, jb3);
    }
    if (qk == 0) {
        int base = row0 * NCAND + bx * 4;
        g_pv[base + 0] = (float)va0; g_pi[base + 0] = ja0;
        g_pv[base + 1] = (float)va1; g_pi[base + 1] = ja1;
        g_pv[base + 2] = (float)va2; g_pi[base + 2] = ja2;
        g_pv[base + 3] = (float)va3; g_pi[base + 3] = ja3;
        base = (row0 + 8) * NCAND + bx * 4;
        g_pv[base + 0] = (float)vb0; g_pi[base + 0] = jb0;
        g_pv[base + 1] = (float)vb1; g_pi[base + 1] = jb1;
        g_pv[base + 2] = (float)vb2; g_pi[base + 2] = jb2;
        g_pv[base + 3] = (float)vb3; g_pi[base + 3] = jb3;
    }
}

// ---------------- kernel 3: parallel merge + exact rescore + top-3 ----------
__global__ void merge_rescore_kernel(const float* __restrict__ w,
                                     const int* __restrict__ label) {
    __shared__ float cv[NCAND];
    __shared__ int   ci[NCAND];
    __shared__ float qrow[DD];
    __shared__ float c32v[32];
    __shared__ int   c32i[32];
    __shared__ float exv[32];
    int q = blockIdx.x, t = threadIdx.x;
    int wid = t >> 5, lane = t & 31;
    qrow[t] = g_qn[q * DD + t];
    for (int j = t; j < NCAND; j += 256) {
        cv[j] = g_pv[q * NCAND + j];
        ci[j] = g_pi[q * NCAND + j];
    }
    __syncthreads();

    float t0 = -FLT_MAX, t1 = -FLT_MAX, t2 = -FLT_MAX, t3 = -FLT_MAX;
    int   i0 = 0x7fffffff, i1 = 0x7fffffff, i2 = 0x7fffffff, i3 = 0x7fffffff;
    const int lo = wid * 74, hi = lo + 74;
    for (int j = lo + lane; j < hi; j += 32)
        ins4f(cv[j], ci[j], t0, i0, t1, i1, t2, i2, t3, i3);
    #pragma unroll
    for (int m = 16; m >= 1; m >>= 1) {
        float r0 = __shfl_xor_sync(0xffffffffu, t0, m);
        float r1 = __shfl_xor_sync(0xffffffffu, t1, m);
        float r2 = __shfl_xor_sync(0xffffffffu, t2, m);
        float r3 = __shfl_xor_sync(0xffffffffu, t3, m);
        int   s0 = __shfl_xor_sync(0xffffffffu, i0, m);
        int   s1 = __shfl_xor_sync(0xffffffffu, i1, m);
        int   s2 = __shfl_xor_sync(0xffffffffu, i2, m);
        int   s3 = __shfl_xor_sync(0xffffffffu, i3, m);
        ins4f(r0, s0, t0, i0, t1, i1, t2, i2, t3, i3);
        ins4f(r1, s1, t0, i0, t1, i1, t2, i2, t3, i3);
        ins4f(r2, s2, t0, i0, t1, i1, t2, i2, t3, i3);
        ins4f(r3, s3, t0, i0, t1, i1, t2, i2, t3, i3);
    }
    if (lane == 0) {
        c32v[wid * 4 + 0] = t0; c32i[wid * 4 + 0] = i0;
        c32v[wid * 4 + 1] = t1; c32i[wid * 4 + 1] = i1;
        c32v[wid * 4 + 2] = t2; c32i[wid * 4 + 2] = i2;
        c32v[wid * 4 + 3] = t3; c32i[wid * 4 + 3] = i3;
    }
    __syncthreads();

    {
        int c = t >> 3, sub = t & 7;
        int idx = c32i[c];
        float acc = 0.f;
        #pragma unroll
        for (int dd = 0; dd < 32; dd++) {
            int d = sub * 32 + dd;
            acc += qrow[d] * w[(size_t)d * NN + idx];
        }
        #pragma unroll
        for (int m = 4; m >= 1; m >>= 1)
            acc += __shfl_xor_sync(0xffffffffu, acc, m, 8);
        if (sub == 0) exv[c] = acc;
    }
    __syncthreads();

    if (t == 0) {
        float f0 = -FLT_MAX, f1 = -FLT_MAX, f2 = -FLT_MAX;
        int   j0 = 0x7fffffff, j1 = 0x7fffffff, j2 = 0x7fffffff;
        for (int k = 0; k < 32; k++)
            ins3(exv[k], c32i[k], f0, j0, f1, j1, f2, j2);
        g_score[q * 3 + 0] = f0; g_idx[q * 3 + 0] = j0; g_lab[q * 3 + 0] = label[j0];
        g_score[q * 3 + 1] = f1; g_idx[q * 3 + 1] = j1; g_lab[q * 3 + 1] = label[j1];
        g_score[q * 3 + 2] = f2; g_idx[q * 3 + 2] = j2; g_lab[q * 3 + 2] = label[j2];
    }
}

// ---------------- kernel 4: build H (gather) ---------------------------------
__global__ void build_h_kernel(const float* __restrict__ queries,
                               const float* __restrict__ w) {
    int s = blockIdx.x, d = threadIdx.x;
    int b = s / KK;
    int lab = g_lab[s];
    float score = g_score[s];
    int idx = g_idx[s];
    float* Hrow = &g_H[s * 3 * DD];
    Hrow[d]          = (d == lab) ? score : 0.f;
    Hrow[DD + d]     = queries[b * DD + d];
    Hrow[2 * DD + d] = w[(size_t)d * NN + idx];
}

// ---------------- tail (proven) ----------------------------------------------
__global__ void qkv_kernel(const float* __restrict__ Wq, const float* __restrict__ bq,
                           const float* __restrict__ Wk, const float* __restrict__ bk,
                           const float* __restrict__ Wv, const float* __restrict__ bv) {
    __shared__ float h[16][DD];
    int r0 = blockIdx.x * 16, t = threadIdx.x;
    #pragma unroll
    for (int i = 0; i < 16; i++) h[i][t] = g_H[(r0 + i) * DD + t];
    __syncthreads();
    float aq[16], ak[16], av[16];
    #pragma unroll
    for (int i = 0; i < 16; i++) { aq[i] = bq[t]; ak[i] = bk[t]; av[i] = bv[t]; }
    for (int d = 0; d < DD; d++) {
        float wq = Wq[d * DD + t], wk = Wk[d * DD + t], wv = Wv[d * DD + t];
        #pragma unroll
        for (int i = 0; i < 16; i++) {
            float hv = h[i][d];
            aq[i] += hv * wq; ak[i] += hv * wk; av[i] += hv * wv;
        }
    }
    #pragma unroll
    for (int i = 0; i < 16; i++) {
        g_Qb[(r0 + i) * DD + t] = aq[i];
        g_Kb[(r0 + i) * DD + t] = ak[i];
        g_Vb[(r0 + i) * DD + t] = av[i];
    }
}

__global__ void attn_kernel() {
    __shared__ float q[3][DD], k[3][DD], v[3][DD], a[9];
    int s = blockIdx.x, t = threadIdx.x;
    int base = s * 3 * DD;
    #pragma unroll
    for (int i = 0; i < 3; i++) {
        q[i][t] = g_Qb[base + i * DD + t];
        k[i][t] = g_Kb[base + i * DD + t];
        v[i][t] = g_Vb[base + i * DD + t];
    }
    __syncthreads();
    if (t < 9) {
        int i = t / 3, j = t % 3;
        float acc = 0.f;
        for (int d = 0; d < DD; d++) acc += q[i][d] * k[j][d];
        a[t] = acc * 0.125f;
    }
    __syncthreads();
    if (t < 3) {
        float m0 = fmaxf(a[t*3], fmaxf(a[t*3+1], a[t*3+2]));
        float e0 = expf(a[t*3] - m0), e1 = expf(a[t*3+1] - m0), e2 = expf(a[t*3+2] - m0);
        float inv = 1.f / (e0 + e1 + e2);
        a[t*3] = e0 * inv; a[t*3+1] = e1 * inv; a[t*3+2] = e2 * inv;
    }
    __syncthreads();
    #pragma unroll
    for (int i = 0; i < 3; i++)
        g_Ab[base + i * DD + t] = a[i*3] * v[0][t] + a[i*3+1] * v[1][t] + a[i*3+2] * v[2][t];
}

__global__ void oproj_kernel(const float* __restrict__ Wo, const float* __restrict__ bo) {
    __shared__ float h[16][DD];
    int r0 = blockIdx.x * 16, t = threadIdx.x;
    #pragma unroll
    for (int i = 0; i < 16; i++) h[i][t] = g_Ab[(r0 + i) * DD + t];
    __syncthreads();
    float ao[16];
    #pragma unroll
    for (int i = 0; i < 16; i++) ao[i] = bo[t];
    for (int d = 0; d < DD; d++) {
        float wo = Wo[d * DD + t];
        #pragma unroll
        for (int i = 0; i < 16; i++) ao[i] += h[i][d] * wo;
    }
    #pragma unroll
    for (int i = 0; i < 16; i++) g_H[(r0 + i) * DD + t] = ao[i];
}

__global__ void dense_kernel(const float* __restrict__ W, const float* __restrict__ b) {
    __shared__ float h[DD];
    int s = blockIdx.x, t = threadIdx.x;
    h[t] = g_H[s * 3 * DD + t];
    __syncthreads();
    float acc = b[t];
    for (int d = 0; d < DD; d++) acc += h[d] * W[d * DD + t];
    g_x[s * DD + t] = tanhf(acc);
}

__global__ void final_kernel(const float* __restrict__ out_w,
                             const float* __restrict__ out_b,
                             float* __restrict__ out) {
    __shared__ float lg[36];
    int b = blockIdx.x, t = threadIdx.x;
    int k = t / NLAB, l = t % NLAB;
    float acc = out_b[l];
    const float* x = &g_x[(b * 3 + k) * DD];
    for (int d = 0; d < DD; d++) acc += x[d] * out_w[d * NLAB + l];
    lg[t] = acc;
    __syncthreads();
    if (t < NLAB) {
        float mean = (lg[t] + lg[NLAB + t] + lg[2 * NLAB + t]) * (1.f / 3.f);
        int l0 = g_lab[b * 3], l1 = g_lab[b * 3 + 1], l2 = g_lab[b * 3 + 2];
        float cnt = (float)((l0 == t) + (l1 == t) + (l2 == t));
        out[b * NLAB + t] = 0.5f * mean + 0.5f * (cnt * (1.f / 3.f));
    }
}

// ---------------- launcher ---------------------------------------------------
extern "C" void kernel_launch(void* const* d_in, const int* in_sizes, int n_in,
                              void* d_out, int out_size) {
    const float* queries = (const float*)d_in[0];
    const float* weight  = (const float*)d_in[1];
    const int*   label   = (const int*)  d_in[2];
    const float* Wq      = (const float*)d_in[3];
    const float* bq      = (const float*)d_in[4];
    const float* Wk      = (const float*)d_in[5];
    const float* bk      = (const float*)d_in[6];
    const float* Wv      = (const float*)d_in[7];
    const float* bv      = (const float*)d_in[8];
    const float* Wo      = (const float*)d_in[9];
    const float* bo      = (const float*)d_in[10];
    const float* dense_w = (const float*)d_in[11];
    const float* dense_b = (const float*)d_in[12];
    const float* out_w   = (const float*)d_in[13];
    const float* out_b   = (const float*)d_in[14];
    float* out = (float*)d_out;

    normalize_kernel<<<BB, DD>>>(queries);
    sims_mma_kernel<<<NCTA, 512>>>(weight);
    merge_rescore_kernel<<<BB, 256>>>(weight, label);
    build_h_kernel<<<NSEQ, DD>>>(queries, weight);

    for (int l = 0; l < 2; l++) {
        qkv_kernel<<<MROWS / 16, DD>>>(Wq + l * DD * DD, bq + l * DD,
                                       Wk + l * DD * DD, bk + l * DD,
                                       Wv + l * DD * DD, bv + l * DD);
        attn_kernel<<<NSEQ, DD>>>();
        oproj_kernel<<<MROWS / 16, DD>>>(Wo + l * DD * DD, bo + l * DD);
    }
    dense_kernel<<<NSEQ, DD>>>(dense_w, dense_b);
    final_kernel<<<BB, 36>>>(out_w, out_b, out);
}

// round 15
// speedup vs baseline: 1.2807x; 1.2785x over previous
#include <cuda_runtime.h>
#include <cuda_bf16.h>
#include <cuda_fp16.h>
#include <float.h>
#include <math.h>
#include <stdint.h>

// ---------------------------------------------------------------------------
// MEATransformer. Round 14: revert int8 (regressed; IMMA rt~128 on sm_103a).
// Base = R12 fused bf16 kernel (759.7us). Single change: mma kind switched to
// m16n8k16.f16.f16.f16.f16 (fp16 accumulate, 2 C-regs) betting on 2x rate of
// the throttled legacy tensor path. Sieve-only precision (exact fp32 rescore
// of union-32 unchanged -> identical output).
// ---------------------------------------------------------------------------

#define NN       500000
#define DD       256
#define BB       256
#define KK       3
#define NLAB     12
#define NSEQ     768
#define MROWS    2304

#define NCHUNK   15625          // 500000/32 col-chunks
#define NCTA     148
#define NCAND    (NCTA * 4)     // 592 candidates per query

// ---------------- device scratch --------------------------------------------
__device__ float  g_qn [BB * DD];
__device__ __half g_qh [BB * DD];
__device__ float g_pv   [BB * NCAND];
__device__ int   g_pi   [BB * NCAND];
__device__ float g_score[NSEQ];
__device__ int   g_idx  [NSEQ];
__device__ int   g_lab  [NSEQ];
__device__ float g_H    [MROWS * DD];
__device__ float g_Qb   [MROWS * DD];
__device__ float g_Kb   [MROWS * DD];
__device__ float g_Vb   [MROWS * DD];
__device__ float g_Ab   [MROWS * DD];
__device__ float g_x    [NSEQ * DD];

// ---------------- helpers ----------------------------------------------------
__device__ __forceinline__ uint32_t pack_f16x2(float lo, float hi) {
    __half2 p = __floats2half2_rn(lo, hi);   // p.x = lo, p.y = hi
    uint32_t r;
    memcpy(&r, &p, 4);
    return r;
}

// m16n8k16, f16 inputs, f16 accumulate: D/C = 2 b32 regs (f16x2 each).
// D0 = {c(row g, col 2q), c(row g, col 2q+1)}, D1 = rows +8.
__device__ __forceinline__ void mma_f16acc(uint32_t& D0, uint32_t& D1,
                                           uint32_t a0, uint32_t a1, uint32_t a2, uint32_t a3,
                                           uint32_t b0, uint32_t b1) {
    asm volatile("mma.sync.aligned.m16n8k16.row.col.f16.f16.f16.f16 "
                 "{%0,%1}, {%2,%3,%4,%5}, {%6,%7}, {%0,%1};"
                 : "+r"(D0), "+r"(D1)
                 : "r"(a0), "r"(a1), "r"(a2), "r"(a3), "r"(b0), "r"(b1));
}

__device__ __forceinline__ bool better(float v1, int i1, float v2, int i2) {
    return (v1 > v2) || (v1 == v2 && i1 < i2);   // jax top_k tie-break
}
__device__ __forceinline__ void ins3(float v, int i,
                                     float& v0, int& i0, float& v1, int& i1,
                                     float& v2, int& i2) {
    if (better(v, i, v2, i2)) {
        if (better(v, i, v1, i1)) {
            v2 = v1; i2 = i1;
            if (better(v, i, v0, i0)) { v1 = v0; i1 = i0; v0 = v; i0 = i; }
            else                      { v1 = v;  i1 = i; }
        } else { v2 = v; i2 = i; }
    }
}
__device__ __forceinline__ void ins4f(float v, int i,
                                      float& t0, int& i0, float& t1, int& i1,
                                      float& t2, int& i2, float& t3, int& i3) {
    if (v <= t3) return;
    if (v > t1) {
        if (v > t0) { t3 = t2; i3 = i2; t2 = t1; i2 = i1; t1 = t0; i1 = i0; t0 = v; i0 = i; }
        else        { t3 = t2; i3 = i2; t2 = t1; i2 = i1; t1 = v;  i1 = i; }
    } else {
        if (v > t2) { t3 = t2; i3 = i2; t2 = v; i2 = i; }
        else        { t3 = v;  i3 = i; }
    }
}

// ---------------- kernel 1: normalize queries (+ f16 copy) -------------------
__global__ void normalize_kernel(const float* __restrict__ q) {
    __shared__ float ws[8];
    int b = blockIdx.x, t = threadIdx.x;
    float v = q[b * DD + t];
    float s = v * v;
    #pragma unroll
    for (int o = 16; o; o >>= 1) s += __shfl_xor_sync(0xffffffffu, s, o);
    if ((t & 31) == 0) ws[t >> 5] = s;
    __syncthreads();
    float tot = 0.f;
    #pragma unroll
    for (int w = 0; w < 8; w++) tot += ws[w];
    float qn = v / sqrtf(tot);
    g_qn[b * DD + t] = qn;
    g_qh[b * DD + t] = __float2half(qn);
}

// ---------------- kernel 2: fused sims (fp32 load -> f16 frag -> mma.sync) ---
// Identical structure/layout to the proven R12 bf16 kernel; only the pack
// (f16x2) and mma kind (f16 accumulate, 2 C-regs) changed.
__global__ void __launch_bounds__(512, 1) sims_mma_kernel(const float* __restrict__ w) {
    __shared__ uint4 sB[2][1024];
    const int tid = threadIdx.x;
    const int wid = tid >> 5, lane = tid & 31;
    const int g = lane >> 2, qk = lane & 3;
    const int bx = blockIdx.x;
    const int row0 = wid * 16 + g;

    // ---- persistent A fragments: 16 ksteps x 4 regs ----
    uint32_t Af[16][4];
    const uint32_t* qh = (const uint32_t*)g_qh;
    #pragma unroll
    for (int ks = 0; ks < 16; ks++) {
        int k0 = ks * 16 + qk * 2;
        Af[ks][0] = qh[(row0 * DD + k0) >> 1];
        Af[ks][1] = qh[((row0 + 8) * DD + k0) >> 1];
        Af[ks][2] = qh[(row0 * DD + k0 + 8) >> 1];
        Af[ks][3] = qh[((row0 + 8) * DD + k0 + 8) >> 1];
    }

    const int ntiles = (NCHUNK - bx + NCTA - 1) / NCTA;

    float va0 = -FLT_MAX, va1 = -FLT_MAX, va2 = -FLT_MAX, va3 = -FLT_MAX;
    int   ja0 = 0x7fffffff, ja1 = 0x7fffffff, ja2 = 0x7fffffff, ja3 = 0x7fffffff;
    float vb0 = -FLT_MAX, vb1 = -FLT_MAX, vb2 = -FLT_MAX, vb3 = -FLT_MAX;
    int   jb0 = 0x7fffffff, jb1 = 0x7fffffff, jb2 = 0x7fffffff, jb3 = 0x7fffffff;

    float4 pf[4];   // 2 assignments x 2 d-rows prefetch

    auto ldg_tile = [&](int tile) {
        const size_t col0 = (size_t)tile * 32;
        #pragma unroll
        for (int p = 0; p < 2; p++) {
            int u = tid + p * 512;
            int d  = (u >> 3) * 2;
            int n4 = (u & 7) * 4;
            const float* base = w + (size_t)d * NN + col0 + n4;
            pf[p * 2]     = *(const float4*)(base);
            pf[p * 2 + 1] = *(const float4*)(base + NN);
        }
    };
    auto sts_tile = [&](int buf) {
        uint32_t* dst = (uint32_t*)&sB[buf][0];
        #pragma unroll
        for (int p = 0; p < 2; p++) {
            int u = tid + p * 512;
            int d  = (u >> 3) * 2;
            int n4 = (u & 7) * 4;
            const int ks2 = d >> 5;
            const int rr = (((d >> 4) & 1) << 1) | ((d >> 3) & 1);
            const int lane_lo = (d & 7) >> 1;
            const float* a = (const float*)&pf[p * 2];
            const float* b = (const float*)&pf[p * 2 + 1];
            #pragma unroll
            for (int i = 0; i < 4; i++) {
                int nl = n4 + i;
                int lane2 = ((nl & 7) << 2) | lane_lo;
                int f = ((nl >> 3) * 8 + ks2) * 32 + lane2;
                dst[f * 4 + rr] = pack_f16x2(a[i], b[i]);
            }
        }
    };

    ldg_tile(bx);   // prologue

    for (int t = 0; t < ntiles; t++) {
        const int buf = t & 1;
        sts_tile(buf);
        __syncthreads();
        if (t + 1 < ntiles) ldg_tile(bx + (t + 1) * NCTA);

        const int colbase = (bx + t * NCTA) * 32 + qk * 2;
        #pragma unroll
        for (int nt = 0; nt < 4; nt++) {
            uint32_t D0 = 0u, D1 = 0u;   // f16x2 accumulators (zero = 0.0h pair)
            #pragma unroll
            for (int ks2 = 0; ks2 < 8; ks2++) {
                uint4 bf = sB[buf][(nt * 8 + ks2) * 32 + lane];
                mma_f16acc(D0, D1,
                           Af[2*ks2][0], Af[2*ks2][1], Af[2*ks2][2], Af[2*ks2][3],
                           bf.x, bf.y);
                mma_f16acc(D0, D1,
                           Af[2*ks2+1][0], Af[2*ks2+1][1], Af[2*ks2+1][2], Af[2*ks2+1][3],
                           bf.z, bf.w);
            }
            float2 fa = __half22float2(*(__half2*)&D0);   // row0:   col+0, col+1
            float2 fb = __half22float2(*(__half2*)&D1);   // row0+8: col+0, col+1
            int c0 = colbase + nt * 8;
            ins4f(fa.x, c0,     va0, ja0, va1, ja1, va2, ja2, va3, ja3);
            ins4f(fa.y, c0 + 1, va0, ja0, va1, ja1, va2, ja2, va3, ja3);
            ins4f(fb.x, c0,     vb0, jb0, vb1, jb1, vb2, jb2, vb3, jb3);
            ins4f(fb.y, c0 + 1, vb0, jb0, vb1, jb1, vb2, jb2, vb3, jb3);
        }
        __syncthreads();   // all warps done with sB[buf] before next sts_tile
    }

    // ---- merge top-4 across the 4 lanes of each quad ----
    #pragma unroll
    for (int m = 1; m <= 2; m <<= 1) {
        float r0 = __shfl_xor_sync(0xffffffffu, va0, m, 4);
        float r1 = __shfl_xor_sync(0xffffffffu, va1, m, 4);
        float r2 = __shfl_xor_sync(0xffffffffu, va2, m, 4);
        float r3 = __shfl_xor_sync(0xffffffffu, va3, m, 4);
        int   s0 = __shfl_xor_sync(0xffffffffu, ja0, m, 4);
        int   s1 = __shfl_xor_sync(0xffffffffu, ja1, m, 4);
        int   s2 = __shfl_xor_sync(0xffffffffu, ja2, m, 4);
        int   s3 = __shfl_xor_sync(0xffffffffu, ja3, m, 4);
        ins4f(r0, s0, va0, ja0, va1, ja1, va2, ja2, va3, ja3);
        ins4f(r1, s1, va0, ja0, va1, ja1, va2, ja2, va3, ja3);
        ins4f(r2, s2, va0, ja0, va1, ja1, va2, ja2, va3, ja3);
        ins4f(r3, s3, va0, ja0, va1, ja1, va2, ja2, va3, ja3);
        r0 = __shfl_xor_sync(0xffffffffu, vb0, m, 4);
        r1 = __shfl_xor_sync(0xffffffffu, vb1, m, 4);
        r2 = __shfl_xor_sync(0xffffffffu, vb2, m, 4);
        r3 = __shfl_xor_sync(0xffffffffu, vb3, m, 4);
        s0 = __shfl_xor_sync(0xffffffffu, jb0, m, 4);
        s1 = __shfl_xor_sync(0xffffffffu, jb1, m, 4);
        s2 = __shfl_xor_sync(0xffffffffu, jb2, m, 4);
        s3 = __shfl_xor_sync(0xffffffffu, jb3, m, 4);
        ins4f(r0, s0, vb0, jb0, vb1, jb1, vb2, jb2, vb3, jb3);
        ins4f(r1, s1, vb0, jb0, vb1, jb1, vb2, jb2, vb3, jb3);
        ins4f(r2, s2, vb0, jb0, vb1, jb1, vb2, jb2, vb3, jb3);
        ins4f(r3, s3, vb0, jb0, vb1, jb1, vb2, jb2, vb3, jb3);
    }
    if (qk == 0) {
        int base = row0 * NCAND + bx * 4;
        g_pv[base + 0] = va0; g_pi[base + 0] = ja0;
        g_pv[base + 1] = va1; g_pi[base + 1] = ja1;
        g_pv[base + 2] = va2; g_pi[base + 2] = ja2;
        g_pv[base + 3] = va3; g_pi[base + 3] = ja3;
        base = (row0 + 8) * NCAND + bx * 4;
        g_pv[base + 0] = vb0; g_pi[base + 0] = jb0;
        g_pv[base + 1] = vb1; g_pi[base + 1] = jb1;
        g_pv[base + 2] = vb2; g_pi[base + 2] = jb2;
        g_pv[base + 3] = vb3; g_pi[base + 3] = jb3;
    }
}

// ---------------- kernel 3: parallel merge + exact rescore + top-3 ----------
__global__ void merge_rescore_kernel(const float* __restrict__ w,
                                     const int* __restrict__ label) {
    __shared__ float cv[NCAND];
    __shared__ int   ci[NCAND];
    __shared__ float qrow[DD];
    __shared__ float c32v[32];
    __shared__ int   c32i[32];
    __shared__ float exv[32];
    int q = blockIdx.x, t = threadIdx.x;
    int wid = t >> 5, lane = t & 31;
    qrow[t] = g_qn[q * DD + t];
    for (int j = t; j < NCAND; j += 256) {
        cv[j] = g_pv[q * NCAND + j];
        ci[j] = g_pi[q * NCAND + j];
    }
    __syncthreads();

    float t0 = -FLT_MAX, t1 = -FLT_MAX, t2 = -FLT_MAX, t3 = -FLT_MAX;
    int   i0 = 0x7fffffff, i1 = 0x7fffffff, i2 = 0x7fffffff, i3 = 0x7fffffff;
    const int lo = wid * 74, hi = lo + 74;
    for (int j = lo + lane; j < hi; j += 32)
        ins4f(cv[j], ci[j], t0, i0, t1, i1, t2, i2, t3, i3);
    #pragma unroll
    for (int m = 16; m >= 1; m >>= 1) {
        float r0 = __shfl_xor_sync(0xffffffffu, t0, m);
        float r1 = __shfl_xor_sync(0xffffffffu, t1, m);
        float r2 = __shfl_xor_sync(0xffffffffu, t2, m);
        float r3 = __shfl_xor_sync(0xffffffffu, t3, m);
        int   s0 = __shfl_xor_sync(0xffffffffu, i0, m);
        int   s1 = __shfl_xor_sync(0xffffffffu, i1, m);
        int   s2 = __shfl_xor_sync(0xffffffffu, i2, m);
        int   s3 = __shfl_xor_sync(0xffffffffu, i3, m);
        ins4f(r0, s0, t0, i0, t1, i1, t2, i2, t3, i3);
        ins4f(r1, s1, t0, i0, t1, i1, t2, i2, t3, i3);
        ins4f(r2, s2, t0, i0, t1, i1, t2, i2, t3, i3);
        ins4f(r3, s3, t0, i0, t1, i1, t2, i2, t3, i3);
    }
    if (lane == 0) {
        c32v[wid * 4 + 0] = t0; c32i[wid * 4 + 0] = i0;
        c32v[wid * 4 + 1] = t1; c32i[wid * 4 + 1] = i1;
        c32v[wid * 4 + 2] = t2; c32i[wid * 4 + 2] = i2;
        c32v[wid * 4 + 3] = t3; c32i[wid * 4 + 3] = i3;
    }
    __syncthreads();

    {
        int c = t >> 3, sub = t & 7;
        int idx = c32i[c];
        float acc = 0.f;
        #pragma unroll
        for (int dd = 0; dd < 32; dd++) {
            int d = sub * 32 + dd;
            acc += qrow[d] * w[(size_t)d * NN + idx];
        }
        #pragma unroll
        for (int m = 4; m >= 1; m >>= 1)
            acc += __shfl_xor_sync(0xffffffffu, acc, m, 8);
        if (sub == 0) exv[c] = acc;
    }
    __syncthreads();

    if (t == 0) {
        float f0 = -FLT_MAX, f1 = -FLT_MAX, f2 = -FLT_MAX;
        int   j0 = 0x7fffffff, j1 = 0x7fffffff, j2 = 0x7fffffff;
        for (int k = 0; k < 32; k++)
            ins3(exv[k], c32i[k], f0, j0, f1, j1, f2, j2);
        g_score[q * 3 + 0] = f0; g_idx[q * 3 + 0] = j0; g_lab[q * 3 + 0] = label[j0];
        g_score[q * 3 + 1] = f1; g_idx[q * 3 + 1] = j1; g_lab[q * 3 + 1] = label[j1];
        g_score[q * 3 + 2] = f2; g_idx[q * 3 + 2] = j2; g_lab[q * 3 + 2] = label[j2];
    }
}

// ---------------- kernel 4: build H (gather) ---------------------------------
__global__ void build_h_kernel(const float* __restrict__ queries,
                               const float* __restrict__ w) {
    int s = blockIdx.x, d = threadIdx.x;
    int b = s / KK;
    int lab = g_lab[s];
    float score = g_score[s];
    int idx = g_idx[s];
    float* Hrow = &g_H[s * 3 * DD];
    Hrow[d]          = (d == lab) ? score : 0.f;
    Hrow[DD + d]     = queries[b * DD + d];
    Hrow[2 * DD + d] = w[(size_t)d * NN + idx];
}

// ---------------- tail (proven) ----------------------------------------------
__global__ void qkv_kernel(const float* __restrict__ Wq, const float* __restrict__ bq,
                           const float* __restrict__ Wk, const float* __restrict__ bk,
                           const float* __restrict__ Wv, const float* __restrict__ bv) {
    __shared__ float h[16][DD];
    int r0 = blockIdx.x * 16, t = threadIdx.x;
    #pragma unroll
    for (int i = 0; i < 16; i++) h[i][t] = g_H[(r0 + i) * DD + t];
    __syncthreads();
    float aq[16], ak[16], av[16];
    #pragma unroll
    for (int i = 0; i < 16; i++) { aq[i] = bq[t]; ak[i] = bk[t]; av[i] = bv[t]; }
    for (int d = 0; d < DD; d++) {
        float wq = Wq[d * DD + t], wk = Wk[d * DD + t], wv = Wv[d * DD + t];
        #pragma unroll
        for (int i = 0; i < 16; i++) {
            float hv = h[i][d];
            aq[i] += hv * wq; ak[i] += hv * wk; av[i] += hv * wv;
        }
    }
    #pragma unroll
    for (int i = 0; i < 16; i++) {
        g_Qb[(r0 + i) * DD + t] = aq[i];
        g_Kb[(r0 + i) * DD + t] = ak[i];
        g_Vb[(r0 + i) * DD + t] = av[i];
    }
}

__global__ void attn_kernel() {
    __shared__ float q[3][DD], k[3][DD], v[3][DD], a[9];
    int s = blockIdx.x, t = threadIdx.x;
    int base = s * 3 * DD;
    #pragma unroll
    for (int i = 0; i < 3; i++) {
        q[i][t] = g_Qb[base + i * DD + t];
        k[i][t] = g_Kb[base + i * DD + t];
        v[i][t] = g_Vb[base + i * DD + t];
    }
    __syncthreads();
    if (t < 9) {
        int i = t / 3, j = t % 3;
        float acc = 0.f;
        for (int d = 0; d < DD; d++) acc += q[i][d] * k[j][d];
        a[t] = acc * 0.125f;
    }
    __syncthreads();
    if (t < 3) {
        float m0 = fmaxf(a[t*3], fmaxf(a[t*3+1], a[t*3+2]));
        float e0 = expf(a[t*3] - m0), e1 = expf(a[t*3+1] - m0), e2 = expf(a[t*3+2] - m0);
        float inv = 1.f / (e0 + e1 + e2);
        a[t*3] = e0 * inv; a[t*3+1] = e1 * inv; a[t*3+2] = e2 * inv;
    }
    __syncthreads();
    #pragma unroll
    for (int i = 0; i < 3; i++)
        g_Ab[base + i * DD + t] = a[i*3] * v[0][t] + a[i*3+1] * v[1][t] + a[i*3+2] * v[2][t];
}

__global__ void oproj_kernel(const float* __restrict__ Wo, const float* __restrict__ bo) {
    __shared__ float h[16][DD];
    int r0 = blockIdx.x * 16, t = threadIdx.x;
    #pragma unroll
    for (int i = 0; i < 16; i++) h[i][t] = g_Ab[(r0 + i) * DD + t];
    __syncthreads();
    float ao[16];
    #pragma unroll
    for (int i = 0; i < 16; i++) ao[i] = bo[t];
    for (int d = 0; d < DD; d++) {
        float wo = Wo[d * DD + t];
        #pragma unroll
        for (int i = 0; i < 16; i++) ao[i] += h[i][d] * wo;
    }
    #pragma unroll
    for (int i = 0; i < 16; i++) g_H[(r0 + i) * DD + t] = ao[i];
}

__global__ void dense_kernel(const float* __restrict__ W, const float* __restrict__ b) {
    __shared__ float h[DD];
    int s = blockIdx.x, t = threadIdx.x;
    h[t] = g_H[s * 3 * DD + t];
    __syncthreads();
    float acc = b[t];
    for (int d = 0; d < DD; d++) acc += h[d] * W[d * DD + t];
    g_x[s * DD + t] = tanhf(acc);
}

__global__ void final_kernel(const float* __restrict__ out_w,
                             const float* __restrict__ out_b,
                             float* __restrict__ out) {
    __shared__ float lg[36];
    int b = blockIdx.x, t = threadIdx.x;
    int k = t / NLAB, l = t % NLAB;
    float acc = out_b[l];
    const float* x = &g_x[(b * 3 + k) * DD];
    for (int d = 0; d < DD; d++) acc += x[d] * out_w[d * NLAB + l];
    lg[t] = acc;
    __syncthreads();
    if (t < NLAB) {
        float mean = (lg[t] + lg[NLAB + t] + lg[2 * NLAB + t]) * (1.f / 3.f);
        int l0 = g_lab[b * 3], l1 = g_lab[b * 3 + 1], l2 = g_lab[b * 3 + 2];
        float cnt = (float)((l0 == t) + (l1 == t) + (l2 == t));
        out[b * NLAB + t] = 0.5f * mean + 0.5f * (cnt * (1.f / 3.f));
    }
}

// ---------------- launcher ---------------------------------------------------
extern "C" void kernel_launch(void* const* d_in, const int* in_sizes, int n_in,
                              void* d_out, int out_size) {
    const float* queries = (const float*)d_in[0];
    const float* weight  = (const float*)d_in[1];
    const int*   label   = (const int*)  d_in[2];
    const float* Wq      = (const float*)d_in[3];
    const float* bq      = (const float*)d_in[4];
    const float* Wk      = (const float*)d_in[5];
    const float* bk      = (const float*)d_in[6];
    const float* Wv      = (const float*)d_in[7];
    const float* bv      = (const float*)d_in[8];
    const float* Wo      = (const float*)d_in[9];
    const float* bo      = (const float*)d_in[10];
    const float* dense_w = (const float*)d_in[11];
    const float* dense_b = (const float*)d_in[12];
    const float* out_w   = (const float*)d_in[13];
    const float* out_b   = (const float*)d_in[14];
    float* out = (float*)d_out;

    normalize_kernel<<<BB, DD>>>(queries);
    sims_mma_kernel<<<NCTA, 512>>>(weight);
    merge_rescore_kernel<<<BB, 256>>>(weight, label);
    build_h_kernel<<<NSEQ, DD>>>(queries, weight);

    for (int l = 0; l < 2; l++) {
        qkv_kernel<<<MROWS / 16, DD>>>(Wq + l * DD * DD, bq + l * DD,
                                       Wk + l * DD * DD, bk + l * DD,
                                       Wv + l * DD * DD, bv + l * DD);
        attn_kernel<<<NSEQ, DD>>>();
        oproj_kernel<<<MROWS / 16, DD>>>(Wo + l * DD * DD, bo + l * DD);
    }
    dense_kernel<<<NSEQ, DD>>>(dense_w, dense_b);
    final_kernel<<<BB, 36>>>(out_w, out_b, out);
}

// round 16
// speedup vs baseline: 1.3596x; 1.0616x over previous
#include <cuda_runtime.h>
#include <cuda_bf16.h>
#include <cuda_fp16.h>
#include <float.h>
#include <math.h>
#include <stdint.h>

// ---------------------------------------------------------------------------
// MEATransformer. Round 15: ILP experiment on the sims HMMA loop — split each
// nt accumulator chain (16 serial MMAs) into TWO independent 8-deep f16-acc
// chains (even/odd ks2), summed in fp32. Discriminates latency-bound vs
// rate-bound legacy HMMA. Also: single barrier per tile (R7 induction).
// Tail and rescore unchanged (clean attribution).
// ---------------------------------------------------------------------------

#define NN       500000
#define DD       256
#define BB       256
#define KK       3
#define NLAB     12
#define NSEQ     768
#define MROWS    2304

#define NCHUNK   15625          // 500000/32 col-chunks
#define NCTA     148
#define NCAND    (NCTA * 4)     // 592 candidates per query

// ---------------- device scratch --------------------------------------------
__device__ float  g_qn [BB * DD];
__device__ __half g_qh [BB * DD];
__device__ float g_pv   [BB * NCAND];
__device__ int   g_pi   [BB * NCAND];
__device__ float g_score[NSEQ];
__device__ int   g_idx  [NSEQ];
__device__ int   g_lab  [NSEQ];
__device__ float g_H    [MROWS * DD];
__device__ float g_Qb   [MROWS * DD];
__device__ float g_Kb   [MROWS * DD];
__device__ float g_Vb   [MROWS * DD];
__device__ float g_Ab   [MROWS * DD];
__device__ float g_x    [NSEQ * DD];

// ---------------- helpers ----------------------------------------------------
__device__ __forceinline__ uint32_t pack_f16x2(float lo, float hi) {
    __half2 p = __floats2half2_rn(lo, hi);   // p.x = lo, p.y = hi
    uint32_t r;
    memcpy(&r, &p, 4);
    return r;
}

// m16n8k16, f16 inputs, f16 accumulate: D/C = 2 b32 regs (f16x2 each).
__device__ __forceinline__ void mma_f16acc(uint32_t& D0, uint32_t& D1,
                                           uint32_t a0, uint32_t a1, uint32_t a2, uint32_t a3,
                                           uint32_t b0, uint32_t b1) {
    asm volatile("mma.sync.aligned.m16n8k16.row.col.f16.f16.f16.f16 "
                 "{%0,%1}, {%2,%3,%4,%5}, {%6,%7}, {%0,%1};"
                 : "+r"(D0), "+r"(D1)
                 : "r"(a0), "r"(a1), "r"(a2), "r"(a3), "r"(b0), "r"(b1));
}

__device__ __forceinline__ bool better(float v1, int i1, float v2, int i2) {
    return (v1 > v2) || (v1 == v2 && i1 < i2);   // jax top_k tie-break
}
__device__ __forceinline__ void ins3(float v, int i,
                                     float& v0, int& i0, float& v1, int& i1,
                                     float& v2, int& i2) {
    if (better(v, i, v2, i2)) {
        if (better(v, i, v1, i1)) {
            v2 = v1; i2 = i1;
            if (better(v, i, v0, i0)) { v1 = v0; i1 = i0; v0 = v; i0 = i; }
            else                      { v1 = v;  i1 = i; }
        } else { v2 = v; i2 = i; }
    }
}
__device__ __forceinline__ void ins4f(float v, int i,
                                      float& t0, int& i0, float& t1, int& i1,
                                      float& t2, int& i2, float& t3, int& i3) {
    if (v <= t3) return;
    if (v > t1) {
        if (v > t0) { t3 = t2; i3 = i2; t2 = t1; i2 = i1; t1 = t0; i1 = i0; t0 = v; i0 = i; }
        else        { t3 = t2; i3 = i2; t2 = t1; i2 = i1; t1 = v;  i1 = i; }
    } else {
        if (v > t2) { t3 = t2; i3 = i2; t2 = v; i2 = i; }
        else        { t3 = v;  i3 = i; }
    }
}

// ---------------- kernel 1: normalize queries (+ f16 copy) -------------------
__global__ void normalize_kernel(const float* __restrict__ q) {
    __shared__ float ws[8];
    int b = blockIdx.x, t = threadIdx.x;
    float v = q[b * DD + t];
    float s = v * v;
    #pragma unroll
    for (int o = 16; o; o >>= 1) s += __shfl_xor_sync(0xffffffffu, s, o);
    if ((t & 31) == 0) ws[t >> 5] = s;
    __syncthreads();
    float tot = 0.f;
    #pragma unroll
    for (int w = 0; w < 8; w++) tot += ws[w];
    float qn = v / sqrtf(tot);
    g_qn[b * DD + t] = qn;
    g_qh[b * DD + t] = __float2half(qn);
}

// ---------------- kernel 2: fused sims (fp32 load -> f16 frag -> mma.sync) ---
// Structure/layout identical to the proven R12/R15 kernel except:
//   (1) per-nt accumulation split into 2 independent 8-deep chains (ILP),
//   (2) single __syncthreads per tile (induction-safe, see R7).
__global__ void __launch_bounds__(512, 1) sims_mma_kernel(const float* __restrict__ w) {
    __shared__ uint4 sB[2][1024];
    const int tid = threadIdx.x;
    const int wid = tid >> 5, lane = tid & 31;
    const int g = lane >> 2, qk = lane & 3;
    const int bx = blockIdx.x;
    const int row0 = wid * 16 + g;

    // ---- persistent A fragments: 16 ksteps x 4 regs ----
    uint32_t Af[16][4];
    const uint32_t* qh = (const uint32_t*)g_qh;
    #pragma unroll
    for (int ks = 0; ks < 16; ks++) {
        int k0 = ks * 16 + qk * 2;
        Af[ks][0] = qh[(row0 * DD + k0) >> 1];
        Af[ks][1] = qh[((row0 + 8) * DD + k0) >> 1];
        Af[ks][2] = qh[(row0 * DD + k0 + 8) >> 1];
        Af[ks][3] = qh[((row0 + 8) * DD + k0 + 8) >> 1];
    }

    const int ntiles = (NCHUNK - bx + NCTA - 1) / NCTA;

    float va0 = -FLT_MAX, va1 = -FLT_MAX, va2 = -FLT_MAX, va3 = -FLT_MAX;
    int   ja0 = 0x7fffffff, ja1 = 0x7fffffff, ja2 = 0x7fffffff, ja3 = 0x7fffffff;
    float vb0 = -FLT_MAX, vb1 = -FLT_MAX, vb2 = -FLT_MAX, vb3 = -FLT_MAX;
    int   jb0 = 0x7fffffff, jb1 = 0x7fffffff, jb2 = 0x7fffffff, jb3 = 0x7fffffff;

    float4 pf[4];   // 2 assignments x 2 d-rows prefetch

    auto ldg_tile = [&](int tile) {
        const size_t col0 = (size_t)tile * 32;
        #pragma unroll
        for (int p = 0; p < 2; p++) {
            int u = tid + p * 512;
            int d  = (u >> 3) * 2;
            int n4 = (u & 7) * 4;
            const float* base = w + (size_t)d * NN + col0 + n4;
            pf[p * 2]     = *(const float4*)(base);
            pf[p * 2 + 1] = *(const float4*)(base + NN);
        }
    };
    auto sts_tile = [&](int buf) {
        uint32_t* dst = (uint32_t*)&sB[buf][0];
        #pragma unroll
        for (int p = 0; p < 2; p++) {
            int u = tid + p * 512;
            int d  = (u >> 3) * 2;
            int n4 = (u & 7) * 4;
            const int ks2 = d >> 5;
            const int rr = (((d >> 4) & 1) << 1) | ((d >> 3) & 1);
            const int lane_lo = (d & 7) >> 1;
            const float* a = (const float*)&pf[p * 2];
            const float* b = (const float*)&pf[p * 2 + 1];
            #pragma unroll
            for (int i = 0; i < 4; i++) {
                int nl = n4 + i;
                int lane2 = ((nl & 7) << 2) | lane_lo;
                int f = ((nl >> 3) * 8 + ks2) * 32 + lane2;
                dst[f * 4 + rr] = pack_f16x2(a[i], b[i]);
            }
        }
    };

    ldg_tile(bx);   // prologue

    for (int t = 0; t < ntiles; t++) {
        const int buf = t & 1;
        sts_tile(buf);
        __syncthreads();   // single barrier per tile (induction-safe)
        if (t + 1 < ntiles) ldg_tile(bx + (t + 1) * NCTA);

        const int colbase = (bx + t * NCTA) * 32 + qk * 2;
        #pragma unroll
        for (int nt = 0; nt < 4; nt++) {
            // two INDEPENDENT 8-deep accumulation chains (even/odd ks2 step)
            uint32_t Da0 = 0u, Da1 = 0u;
            uint32_t Db0 = 0u, Db1 = 0u;
            #pragma unroll
            for (int ks2 = 0; ks2 < 8; ks2++) {
                uint4 bf = sB[buf][(nt * 8 + ks2) * 32 + lane];
                mma_f16acc(Da0, Da1,
                           Af[2*ks2][0], Af[2*ks2][1], Af[2*ks2][2], Af[2*ks2][3],
                           bf.x, bf.y);
                mma_f16acc(Db0, Db1,
                           Af[2*ks2+1][0], Af[2*ks2+1][1], Af[2*ks2+1][2], Af[2*ks2+1][3],
                           bf.z, bf.w);
            }
            float2 fa1 = __half22float2(*(__half2*)&Da0);
            float2 fa2 = __half22float2(*(__half2*)&Db0);
            float2 fb1 = __half22float2(*(__half2*)&Da1);
            float2 fb2 = __half22float2(*(__half2*)&Db1);
            float fax = fa1.x + fa2.x, fay = fa1.y + fa2.y;   // row0
            float fbx = fb1.x + fb2.x, fby = fb1.y + fb2.y;   // row0+8
            int c0 = colbase + nt * 8;
            ins4f(fax, c0,     va0, ja0, va1, ja1, va2, ja2, va3, ja3);
            ins4f(fay, c0 + 1, va0, ja0, va1, ja1, va2, ja2, va3, ja3);
            ins4f(fbx, c0,     vb0, jb0, vb1, jb1, vb2, jb2, vb3, jb3);
            ins4f(fby, c0 + 1, vb0, jb0, vb1, jb1, vb2, jb2, vb3, jb3);
        }
    }

    // ---- merge top-4 across the 4 lanes of each quad ----
    #pragma unroll
    for (int m = 1; m <= 2; m <<= 1) {
        float r0 = __shfl_xor_sync(0xffffffffu, va0, m, 4);
        float r1 = __shfl_xor_sync(0xffffffffu, va1, m, 4);
        float r2 = __shfl_xor_sync(0xffffffffu, va2, m, 4);
        float r3 = __shfl_xor_sync(0xffffffffu, va3, m, 4);
        int   s0 = __shfl_xor_sync(0xffffffffu, ja0, m, 4);
        int   s1 = __shfl_xor_sync(0xffffffffu, ja1, m, 4);
        int   s2 = __shfl_xor_sync(0xffffffffu, ja2, m, 4);
        int   s3 = __shfl_xor_sync(0xffffffffu, ja3, m, 4);
        ins4f(r0, s0, va0, ja0, va1, ja1, va2, ja2, va3, ja3);
        ins4f(r1, s1, va0, ja0, va1, ja1, va2, ja2, va3, ja3);
        ins4f(r2, s2, va0, ja0, va1, ja1, va2, ja2, va3, ja3);
        ins4f(r3, s3, va0, ja0, va1, ja1, va2, ja2, va3, ja3);
        r0 = __shfl_xor_sync(0xffffffffu, vb0, m, 4);
        r1 = __shfl_xor_sync(0xffffffffu, vb1, m, 4);
        r2 = __shfl_xor_sync(0xffffffffu, vb2, m, 4);
        r3 = __shfl_xor_sync(0xffffffffu, vb3, m, 4);
        s0 = __shfl_xor_sync(0xffffffffu, jb0, m, 4);
        s1 = __shfl_xor_sync(0xffffffffu, jb1, m, 4);
        s2 = __shfl_xor_sync(0xffffffffu, jb2, m, 4);
        s3 = __shfl_xor_sync(0xffffffffu, jb3, m, 4);
        ins4f(r0, s0, vb0, jb0, vb1, jb1, vb2, jb2, vb3, jb3);
        ins4f(r1, s1, vb0, jb0, vb1, jb1, vb2, jb2, vb3, jb3);
        ins4f(r2, s2, vb0, jb0, vb1, jb1, vb2, jb2, vb3, jb3);
        ins4f(r3, s3, vb0, jb0, vb1, jb1, vb2, jb2, vb3, jb3);
    }
    if (qk == 0) {
        int base = row0 * NCAND + bx * 4;
        g_pv[base + 0] = va0; g_pi[base + 0] = ja0;
        g_pv[base + 1] = va1; g_pi[base + 1] = ja1;
        g_pv[base + 2] = va2; g_pi[base + 2] = ja2;
        g_pv[base + 3] = va3; g_pi[base + 3] = ja3;
        base = (row0 + 8) * NCAND + bx * 4;
        g_pv[base + 0] = vb0; g_pi[base + 0] = jb0;
        g_pv[base + 1] = vb1; g_pi[base + 1] = jb1;
        g_pv[base + 2] = vb2; g_pi[base + 2] = jb2;
        g_pv[base + 3] = vb3; g_pi[base + 3] = jb3;
    }
}

// ---------------- kernel 3: parallel merge + exact rescore + top-3 ----------
__global__ void merge_rescore_kernel(const float* __restrict__ w,
                                     const int* __restrict__ label) {
    __shared__ float cv[NCAND];
    __shared__ int   ci[NCAND];
    __shared__ float qrow[DD];
    __shared__ float c32v[32];
    __shared__ int   c32i[32];
    __shared__ float exv[32];
    int q = blockIdx.x, t = threadIdx.x;
    int wid = t >> 5, lane = t & 31;
    qrow[t] = g_qn[q * DD + t];
    for (int j = t; j < NCAND; j += 256) {
        cv[j] = g_pv[q * NCAND + j];
        ci[j] = g_pi[q * NCAND + j];
    }
    __syncthreads();

    float t0 = -FLT_MAX, t1 = -FLT_MAX, t2 = -FLT_MAX, t3 = -FLT_MAX;
    int   i0 = 0x7fffffff, i1 = 0x7fffffff, i2 = 0x7fffffff, i3 = 0x7fffffff;
    const int lo = wid * 74, hi = lo + 74;
    for (int j = lo + lane; j < hi; j += 32)
        ins4f(cv[j], ci[j], t0, i0, t1, i1, t2, i2, t3, i3);
    #pragma unroll
    for (int m = 16; m >= 1; m >>= 1) {
        float r0 = __shfl_xor_sync(0xffffffffu, t0, m);
        float r1 = __shfl_xor_sync(0xffffffffu, t1, m);
        float r2 = __shfl_xor_sync(0xffffffffu, t2, m);
        float r3 = __shfl_xor_sync(0xffffffffu, t3, m);
        int   s0 = __shfl_xor_sync(0xffffffffu, i0, m);
        int   s1 = __shfl_xor_sync(0xffffffffu, i1, m);
        int   s2 = __shfl_xor_sync(0xffffffffu, i2, m);
        int   s3 = __shfl_xor_sync(0xffffffffu, i3, m);
        ins4f(r0, s0, t0, i0, t1, i1, t2, i2, t3, i3);
        ins4f(r1, s1, t0, i0, t1, i1, t2, i2, t3, i3);
        ins4f(r2, s2, t0, i0, t1, i1, t2, i2, t3, i3);
        ins4f(r3, s3, t0, i0, t1, i1, t2, i2, t3, i3);
    }
    if (lane == 0) {
        c32v[wid * 4 + 0] = t0; c32i[wid * 4 + 0] = i0;
        c32v[wid * 4 + 1] = t1; c32i[wid * 4 + 1] = i1;
        c32v[wid * 4 + 2] = t2; c32i[wid * 4 + 2] = i2;
        c32v[wid * 4 + 3] = t3; c32i[wid * 4 + 3] = i3;
    }
    __syncthreads();

    {
        int c = t >> 3, sub = t & 7;
        int idx = c32i[c];
        float acc = 0.f;
        #pragma unroll
        for (int dd = 0; dd < 32; dd++) {
            int d = sub * 32 + dd;
            acc += qrow[d] * w[(size_t)d * NN + idx];
        }
        #pragma unroll
        for (int m = 4; m >= 1; m >>= 1)
            acc += __shfl_xor_sync(0xffffffffu, acc, m, 8);
        if (sub == 0) exv[c] = acc;
    }
    __syncthreads();

    if (t == 0) {
        float f0 = -FLT_MAX, f1 = -FLT_MAX, f2 = -FLT_MAX;
        int   j0 = 0x7fffffff, j1 = 0x7fffffff, j2 = 0x7fffffff;
        for (int k = 0; k < 32; k++)
            ins3(exv[k], c32i[k], f0, j0, f1, j1, f2, j2);
        g_score[q * 3 + 0] = f0; g_idx[q * 3 + 0] = j0; g_lab[q * 3 + 0] = label[j0];
        g_score[q * 3 + 1] = f1; g_idx[q * 3 + 1] = j1; g_lab[q * 3 + 1] = label[j1];
        g_score[q * 3 + 2] = f2; g_idx[q * 3 + 2] = j2; g_lab[q * 3 + 2] = label[j2];
    }
}

// ---------------- kernel 4: build H (gather) ---------------------------------
__global__ void build_h_kernel(const float* __restrict__ queries,
                               const float* __restrict__ w) {
    int s = blockIdx.x, d = threadIdx.x;
    int b = s / KK;
    int lab = g_lab[s];
    float score = g_score[s];
    int idx = g_idx[s];
    float* Hrow = &g_H[s * 3 * DD];
    Hrow[d]          = (d == lab) ? score : 0.f;
    Hrow[DD + d]     = queries[b * DD + d];
    Hrow[2 * DD + d] = w[(size_t)d * NN + idx];
}

// ---------------- tail (proven) ----------------------------------------------
__global__ void qkv_kernel(const float* __restrict__ Wq, const float* __restrict__ bq,
                           const float* __restrict__ Wk, const float* __restrict__ bk,
                           const float* __restrict__ Wv, const float* __restrict__ bv) {
    __shared__ float h[16][DD];
    int r0 = blockIdx.x * 16, t = threadIdx.x;
    #pragma unroll
    for (int i = 0; i < 16; i++) h[i][t] = g_H[(r0 + i) * DD + t];
    __syncthreads();
    float aq[16], ak[16], av[16];
    #pragma unroll
    for (int i = 0; i < 16; i++) { aq[i] = bq[t]; ak[i] = bk[t]; av[i] = bv[t]; }
    for (int d = 0; d < DD; d++) {
        float wq = Wq[d * DD + t], wk = Wk[d * DD + t], wv = Wv[d * DD + t];
        #pragma unroll
        for (int i = 0; i < 16; i++) {
            float hv = h[i][d];
            aq[i] += hv * wq; ak[i] += hv * wk; av[i] += hv * wv;
        }
    }
    #pragma unroll
    for (int i = 0; i < 16; i++) {
        g_Qb[(r0 + i) * DD + t] = aq[i];
        g_Kb[(r0 + i) * DD + t] = ak[i];
        g_Vb[(r0 + i) * DD + t] = av[i];
    }
}

__global__ void attn_kernel() {
    __shared__ float q[3][DD], k[3][DD], v[3][DD], a[9];
    int s = blockIdx.x, t = threadIdx.x;
    int base = s * 3 * DD;
    #pragma unroll
    for (int i = 0; i < 3; i++) {
        q[i][t] = g_Qb[base + i * DD + t];
        k[i][t] = g_Kb[base + i * DD + t];
        v[i][t] = g_Vb[base + i * DD + t];
    }
    __syncthreads();
    if (t < 9) {
        int i = t / 3, j = t % 3;
        float acc = 0.f;
        for (int d = 0; d < DD; d++) acc += q[i][d] * k[j][d];
        a[t] = acc * 0.125f;
    }
    __syncthreads();
    if (t < 3) {
        float m0 = fmaxf(a[t*3], fmaxf(a[t*3+1], a[t*3+2]));
        float e0 = expf(a[t*3] - m0), e1 = expf(a[t*3+1] - m0), e2 = expf(a[t*3+2] - m0);
        float inv = 1.f / (e0 + e1 + e2);
        a[t*3] = e0 * inv; a[t*3+1] = e1 * inv; a[t*3+2] = e2 * inv;
    }
    __syncthreads();
    #pragma unroll
    for (int i = 0; i < 3; i++)
        g_Ab[base + i * DD + t] = a[i*3] * v[0][t] + a[i*3+1] * v[1][t] + a[i*3+2] * v[2][t];
}

__global__ void oproj_kernel(const float* __restrict__ Wo, const float* __restrict__ bo) {
    __shared__ float h[16][DD];
    int r0 = blockIdx.x * 16, t = threadIdx.x;
    #pragma unroll
    for (int i = 0; i < 16; i++) h[i][t] = g_Ab[(r0 + i) * DD + t];
    __syncthreads();
    float ao[16];
    #pragma unroll
    for (int i = 0; i < 16; i++) ao[i] = bo[t];
    for (int d = 0; d < DD; d++) {
        float wo = Wo[d * DD + t];
        #pragma unroll
        for (int i = 0; i < 16; i++) ao[i] += h[i][d] * wo;
    }
    #pragma unroll
    for (int i = 0; i < 16; i++) g_H[(r0 + i) * DD + t] = ao[i];
}

__global__ void dense_kernel(const float* __restrict__ W, const float* __restrict__ b) {
    __shared__ float h[DD];
    int s = blockIdx.x, t = threadIdx.x;
    h[t] = g_H[s * 3 * DD + t];
    __syncthreads();
    float acc = b[t];
    for (int d = 0; d < DD; d++) acc += h[d] * W[d * DD + t];
    g_x[s * DD + t] = tanhf(acc);
}

__global__ void final_kernel(const float* __restrict__ out_w,
                             const float* __restrict__ out_b,
                             float* __restrict__ out) {
    __shared__ float lg[36];
    int b = blockIdx.x, t = threadIdx.x;
    int k = t / NLAB, l = t % NLAB;
    float acc = out_b[l];
    const float* x = &g_x[(b * 3 + k) * DD];
    for (int d = 0; d < DD; d++) acc += x[d] * out_w[d * NLAB + l];
    lg[t] = acc;
    __syncthreads();
    if (t < NLAB) {
        float mean = (lg[t] + lg[NLAB + t] + lg[2 * NLAB + t]) * (1.f / 3.f);
        int l0 = g_lab[b * 3], l1 = g_lab[b * 3 + 1], l2 = g_lab[b * 3 + 2];
        float cnt = (float)((l0 == t) + (l1 == t) + (l2 == t));
        out[b * NLAB + t] = 0.5f * mean + 0.5f * (cnt * (1.f / 3.f));
    }
}

// ---------------- launcher ---------------------------------------------------
extern "C" void kernel_launch(void* const* d_in, const int* in_sizes, int n_in,
                              void* d_out, int out_size) {
    const float* queries = (const float*)d_in[0];
    const float* weight  = (const float*)d_in[1];
    const int*   label   = (const int*)  d_in[2];
    const float* Wq      = (const float*)d_in[3];
    const float* bq      = (const float*)d_in[4];
    const float* Wk      = (const float*)d_in[5];
    const float* bk      = (const float*)d_in[6];
    const float* Wv      = (const float*)d_in[7];
    const float* bv      = (const float*)d_in[8];
    const float* Wo      = (const float*)d_in[9];
    const float* bo      = (const float*)d_in[10];
    const float* dense_w = (const float*)d_in[11];
    const float* dense_b = (const float*)d_in[12];
    const float* out_w   = (const float*)d_in[13];
    const float* out_b   = (const float*)d_in[14];
    float* out = (float*)d_out;

    normalize_kernel<<<BB, DD>>>(queries);
    sims_mma_kernel<<<NCTA, 512>>>(weight);
    merge_rescore_kernel<<<BB, 256>>>(weight, label);
    build_h_kernel<<<NSEQ, DD>>>(queries, weight);

    for (int l = 0; l < 2; l++) {
        qkv_kernel<<<MROWS / 16, DD>>>(Wq + l * DD * DD, bq + l * DD,
                                       Wk + l * DD * DD, bk + l * DD,
                                       Wv + l * DD * DD, bv + l * DD);
        attn_kernel<<<NSEQ, DD>>>();
        oproj_kernel<<<MROWS / 16, DD>>>(Wo + l * DD * DD, bo + l * DD);
    }
    dense_kernel<<<NSEQ, DD>>>(dense_w, dense_b);
    final_kernel<<<BB, 36>>>(out_w, out_b, out);
}